// round 9
// baseline (speedup 1.0000x reference)
#include <cuda_runtime.h>

#define NB   2
#define NE   8
#define NPX  4096      // 64*64
#define KTOP 700
#define NG   4
#define NCH  36        // (NE+1)*NG
#define OUTW 256

__device__ int g_topk_idx[NB * KTOP];

__device__ __forceinline__ float frcp(float x) {
    float r;
    asm("rcp.approx.f32 %0, %1;" : "=f"(r) : "f"(x));
    return r;
}

// ---------------------------------------------------------------------------
// Kernel 1: exact top-k by parallel rank counting with composite u64 keys.
// key(e) = (monotonic(val) << 12) | (4095 - e)  -> strictly descending order
// with lax.top_k tie semantics (equal value -> smaller index first), so rank
// is a single u64 compare. Grid (128, NB) x 256 threads: block caches all
// 4096 keys in SMEM; thread (e = bx*32 + tid>>3, s = tid&7) counts slice
// {i : i mod 8 == s} (broadcast-friendly, conflict-free), 3-shuffle reduce,
// rank < 700 scatters directly into sorted position.
// ---------------------------------------------------------------------------
__global__ __launch_bounds__(256)
void topk_rank_kernel(const float* __restrict__ obj,
                      float* __restrict__ scores) {
    __shared__ unsigned long long skey[NPX];   // 32 KB
    const int b   = blockIdx.y;
    const int tid = threadIdx.x;
    const float* p = obj + b * NPX;

    for (int i = tid; i < NPX; i += 256) {
        unsigned u = __float_as_uint(p[i]);
        u ^= (unsigned)(((int)u >> 31) | 0x80000000);   // monotonic map
        skey[i] = ((unsigned long long)u << 12) | (unsigned)(NPX - 1 - i);
    }
    __syncthreads();

    const int e = blockIdx.x * 32 + (tid >> 3);
    const int s = tid & 7;
    const unsigned long long me = skey[e];

    int cnt = 0;
#pragma unroll 8
    for (int t = 0; t < 512; t++)
        cnt += (skey[s + (t << 3)] > me);

    cnt += __shfl_down_sync(0xffffffffu, cnt, 4);
    cnt += __shfl_down_sync(0xffffffffu, cnt, 2);
    cnt += __shfl_down_sync(0xffffffffu, cnt, 1);

    if (s == 0 && cnt < KTOP) {
        const float v = p[e];
        scores[b * KTOP + cnt] = frcp(1.0f + __expf(-v));
        g_topk_idx[b * KTOP + cnt] = e;
    }
}

// ---------------------------------------------------------------------------
// Kernel 2: one block per (b, k), STRIP-PIPELINED so DRAM stores start after
// ~1/8 of the compute instead of after all of it (grid is only 1.6 waves, so
// phase-synchronized blocks left DRAM idle during compute).
// Strip s: compute input rows 8s..8s+7 into low[] (one float2/thread), sync,
// then emit output rows [32s-2, 32s+30) (clamped to [0,256)) whose two y-taps
// are now available. low[] is filled monotonically and never overwritten, so
// emit(s) may overlap compute(s+1) without a second barrier.
// ---------------------------------------------------------------------------
__global__ __launch_bounds__(256, 6)
void mask_kernel(const float* __restrict__ enc,   // (NB, NE, 64, 64)
                 const float* __restrict__ wts,   // (NB, NCH, 64, 64)
                 float* __restrict__ out) {       // (NB, KTOP, 256, 256)
    __shared__ float low[NPX];
    __shared__ float swt[NCH];

    const int k   = blockIdx.x;
    const int b   = blockIdx.y;
    const int tid = threadIdx.x;

    const int pos = g_topk_idx[b * KTOP + k];
    if (tid < NCH) swt[tid] = wts[(b * NCH + tid) * NPX + pos];
    __syncthreads();

    const volatile float* vw = swt;   // force LDS reads, keep registers low
    const float2* encb = (const float2*)(enc + b * NE * NPX);
    float* obase = out + ((size_t)(b * KTOP + k)) * (OUTW * OUTW);
    const int warp = tid >> 5, lane = tid & 31;

#pragma unroll 1
    for (int s = 0; s < 8; s++) {
        // ---- compute input rows 8s .. 8s+7 ----
        {
            const int q = s * 256 + tid;       // float2 index in 64x64 plane
            float2 ev[NE];
#pragma unroll
            for (int e = 0; e < NE; e++)
                ev[e] = __ldg(encb + e * (NPX / 2) + q);

            float px = 1.f, py = 1.f;
#pragma unroll
            for (int g = 0; g < NG; g++) {
                float ax = vw[g * (NE + 1) + NE];
                float ay = ax;
#pragma unroll
                for (int e = 0; e < NE; e++) {
                    const float w = vw[g * (NE + 1) + e];
                    ax = fmaf(w, ev[e].x, ax);
                    ay = fmaf(w, ev[e].y, ay);
                }
                px *= 1.f + __expf(-ax);
                py *= 1.f + __expf(-ay);
            }
            ((float2*)low)[q] = make_float2(frcp(px), frcp(py));
        }
        __syncthreads();

        // ---- emit output rows whose y-taps are ready ----
        const int oy0 = (s == 0) ? 0   : 32 * s - 2;
        const int oy1 = (s == 7) ? 256 : 32 * s + 30;
#pragma unroll 1
        for (int oy = oy0 + warp; oy < oy1; oy += 8) {
            const float yf  = oy * 0.25f - 0.375f;
            const float y0f = floorf(yf);
            const float fy  = yf - y0f;
            int y0 = (int)y0f;     if (y0 < 0)  y0 = 0;
            int y1 = (int)y0f + 1; if (y1 > 63) y1 = 63;
            const float* r0 = low + y0 * 64;
            const float* r1 = low + y1 * 64;
            float4* orow = (float4*)(obase + oy * OUTW);
#pragma unroll
            for (int c = 0; c < 2; c++) {
                const int j  = lane + c * 32;
                const int jp = (j == 0)  ? 0  : j - 1;
                const int jn = (j == 63) ? 63 : j + 1;
                const float vp = fmaf(fy, r1[jp] - r0[jp], r0[jp]);
                const float vc = fmaf(fy, r1[j]  - r0[j],  r0[j]);
                const float vn = fmaf(fy, r1[jn] - r0[jn], r0[jn]);
                const float dp = vp - vc, dn = vn - vc;
                float4 o;
                o.x = fmaf(0.375f, dp, vc);
                o.y = fmaf(0.125f, dp, vc);
                o.z = fmaf(0.125f, dn, vc);
                o.w = fmaf(0.375f, dn, vc);
                __stcs(orow + j, o);
            }
        }
    }
}

// ---------------------------------------------------------------------------
extern "C" void kernel_launch(void* const* d_in, const int* in_sizes, int n_in,
                              void* d_out, int out_size) {
    const float* obj = (const float*)d_in[0];  // objectness_logits (2,1,64,64)
    const float* enc = (const float*)d_in[1];  // mask_encodings   (2,8,64,64)
    const float* wts = (const float*)d_in[2];  // weights          (2,36,64,64)
    float* out    = (float*)d_out;             // m (2,700,256,256) then scores (2,700)
    float* scores = out + (size_t)NB * KTOP * OUTW * OUTW;

    dim3 tg(128, NB);
    topk_rank_kernel<<<tg, 256>>>(obj, scores);
    dim3 grid(KTOP, NB);
    mask_kernel<<<grid, 256>>>(enc, wts, out);
}